// round 9
// baseline (speedup 1.0000x reference)
#include <cuda_runtime.h>
#include <cstdint>

// ---------------------------------------------------------------------------
// Multi-scale triplane encoder: scatter-mean of point features into 3 planes
// per scale. B=8, C=32, scales: (res=64, N=65536), (128, 32768), (256, 16384).
//
// Scatter: red.global.add.v4.f32 into channel-contiguous scratch (p,b,cell,C).
// Transpose: smem transpose (+count divide) -> (B,C,res,res).
//   scale0/1: dense body, MLP=4 front loads, one barrier.
//   scale2:   4-tile pipelined sparse body — counts for tile t+1 prefetched
//             during tile t, so predicated loads never wait on a count fetch.
// Scratch invariant: g_scr/g_cnt ALL-ZERO between kernel_launch calls
// (counts zeroed by their loader thread, touched lines zeroed by predicated
// stores after the barrier). No separate zero pass ever runs.
// ---------------------------------------------------------------------------

#define BATCH 8
#define CDIM 32

#define SCR_TOTAL 66060288          // 264MB scratch (same count as output)
__device__ __align__(16) float g_scr[SCR_TOTAL];
#define CNT_TOTAL 2064384
__device__ __align__(16) float g_cnt[CNT_TOTAL];

// scale bases (floats) — same for scratch and output
#define OFF0 0
#define OFF1 (3 * 8 * 32 * 64 * 64)                 //  3,145,728
#define OFF2 (OFF1 + 3 * 8 * 32 * 128 * 128)        // 15,728,640
#define CNT0 0
#define CNT1 (3 * 8 * 64 * 64)                      //  98,304
#define CNT2 (CNT1 + 3 * 8 * 128 * 128)             // 491,520

// ---------------------------------------------------------------------------
// Index math must match XLA bit-for-bit: x/C -> x*(1/C) (f32 folded), no FMA.
// ---------------------------------------------------------------------------

__device__ __forceinline__ int grid_idx(float v, float res) {
    const float R = (float)(1.0 / (double)1.10001f);
    float u = __fadd_rn(__fmul_rn(v, R), 0.5f);       // no fma contraction
    u = fminf(fmaxf(u, 0.0f), 0.99999f);
    return (int)(__fmul_rn(u, res));
}

__device__ __forceinline__ void red_v4(float* p, float a, float b, float c, float d) {
    asm volatile("red.global.add.v4.f32 [%0], {%1, %2, %3, %4};"
                 :: "l"(p), "f"(a), "f"(b), "f"(c), "f"(d)
                 : "memory");
}

template <int RES, int LOGN>
__device__ __forceinline__ void scatter_body(const float* __restrict__ f,
                                             const float* __restrict__ cd,
                                             int scr_off, int cnt_off, int gid) {
    const int R2 = RES * RES;
    int b = gid >> LOGN;

    // issue all independent loads up front
    float4 feat[CDIM / 4];
    const float4* fv = reinterpret_cast<const float4*>(f + (size_t)gid * CDIM);
#pragma unroll
    for (int i = 0; i < CDIM / 4; i++) feat[i] = fv[i];
    float x = cd[gid * 3 + 0];
    float y = cd[gid * 3 + 1];
    float z = cd[gid * 3 + 2];

    int gx = grid_idx(x, (float)RES);
    int gy = grid_idx(y, (float)RES);
    int gz = grid_idx(z, (float)RES);

    int idx[3];
    idx[0] = gx + RES * gz;   // xz
    idx[1] = gx + RES * gy;   // xy
    idx[2] = gy + RES * gz;   // yz

#pragma unroll
    for (int p = 0; p < 3; p++) {
        atomicAdd(&g_cnt[cnt_off + ((size_t)p * BATCH + b) * R2 + idx[p]], 1.0f);
        float* o = g_scr + scr_off +
                   (((size_t)p * BATCH + b) * R2 + idx[p]) * CDIM;  // 128B line
#pragma unroll
        for (int i = 0; i < CDIM / 4; i++) {
            red_v4(o + 4 * i, feat[i].x, feat[i].y, feat[i].z, feat[i].w);
        }
    }
}

// merged scatter: blocks [0,2048) scale0, [2048,3072) scale1, [3072,3584) scale2
__global__ __launch_bounds__(256)
void scatter_all_kernel(const float* __restrict__ f0, const float* __restrict__ c0,
                        const float* __restrict__ f1, const float* __restrict__ c1,
                        const float* __restrict__ f2, const float* __restrict__ c2) {
    int blk = blockIdx.x;
    int t = threadIdx.x;
    if (blk < 2048) {
        scatter_body<64, 16>(f0, c0, OFF0, CNT0, blk * 256 + t);
    } else if (blk < 3072) {
        scatter_body<128, 15>(f1, c1, OFF1, CNT1, (blk - 2048) * 256 + t);
    } else {
        scatter_body<256, 14>(f2, c2, OFF2, CNT2, (blk - 3072) * 256 + t);
    }
}

// ---------------------------------------------------------------------------
// Dense transpose body (scale0/1): MLP=4 front loads, one barrier.
// ---------------------------------------------------------------------------

template <int RES>
__device__ __forceinline__ void dense_body(float* __restrict__ out,
                                           int scr_off, int cnt_off,
                                           int tile_idx, int b, int p) {
    const int R2 = RES * RES;
    __shared__ float tile[32][33];
    __shared__ float scnt[32];
    __shared__ float crec[32];
    int tx = threadIdx.x, ty = threadIdx.y;
    int cell0 = tile_idx * 32;

    size_t base = ((size_t)p * BATCH + b) * R2;
    float* cnt = g_cnt + cnt_off + base + cell0;
    float* src = g_scr + scr_off + (base + cell0) * CDIM;

    float v[4];
#pragma unroll
    for (int k = 0; k < 4; k++) v[k] = src[(size_t)(ty + 8 * k) * CDIM + tx];

    if (ty == 0) {
        float c = cnt[tx];
        cnt[tx] = 0.0f;                       // restore count invariant
        scnt[tx] = c;
        crec[tx] = __frcp_rn(fmaxf(c, 1.0f));
    }

#pragma unroll
    for (int k = 0; k < 4; k++) tile[ty + 8 * k][tx] = v[k];
    __syncthreads();

#pragma unroll
    for (int k = 0; k < 4; k++) {
        int row = ty + 8 * k;
        if (scnt[row] != 0.0f) src[(size_t)row * CDIM + tx] = 0.0f;
    }

    float* dst = out + base * CDIM + cell0;
    float r = crec[tx];
#pragma unroll
    for (int k = 0; k < 4; k++) {
        int ch = ty + 8 * k;
        dst[(size_t)ch * R2 + tx] = __fmul_rn(tile[tx][ch], r);
    }
}

// ---------------------------------------------------------------------------
// Sparse pipelined body (scale2): 4 consecutive 32-cell tiles per block.
// Counts for tile t+1 are fetched+zeroed during tile t; predicated data loads
// read their predicate from smem (filled one iteration earlier) so they issue
// back-to-back with full MLP.
// ---------------------------------------------------------------------------

__device__ __forceinline__ void sparse_pipe_body(float* __restrict__ out,
                                                 int scr_off, int cnt_off,
                                                 int tile4_idx, int b, int p) {
    const int R2 = 256 * 256;
    __shared__ float tile[32][33];
    __shared__ float scnt[2][32];
    __shared__ float crec[2][32];
    int tx = threadIdx.x, ty = threadIdx.y;
    int cell0 = tile4_idx * 128;

    size_t base = ((size_t)p * BATCH + b) * R2;
    float* cnt = g_cnt + cnt_off + base + cell0;
    float* src = g_scr + scr_off + (base + cell0) * CDIM;
    float* dst0 = out + base * CDIM + cell0;

    // prologue: counts for tile 0
    if (ty == 0) {
        float c = cnt[tx];
        cnt[tx] = 0.0f;
        scnt[0][tx] = c;
        crec[0][tx] = __frcp_rn(fmaxf(c, 1.0f));
    }
    __syncthreads();

#pragma unroll
    for (int t = 0; t < 4; t++) {
        int buf = t & 1;

        // prefetch counts for tile t+1 (latency hidden by this tile's work)
        if (t < 3 && ty == 0) {
            float c = cnt[(t + 1) * 32 + tx];
            cnt[(t + 1) * 32 + tx] = 0.0f;
            scnt[buf ^ 1][tx] = c;
            crec[buf ^ 1][tx] = __frcp_rn(fmaxf(c, 1.0f));
        }

        // predicated front-batched loads (predicate from smem, no global wait)
        float* s = src + (size_t)t * 32 * CDIM;
        bool tch[4];
        float v[4];
#pragma unroll
        for (int k = 0; k < 4; k++) {
            int row = ty + 8 * k;
            tch[k] = (scnt[buf][row] != 0.0f);
            v[k] = tch[k] ? s[(size_t)row * CDIM + tx] : 0.0f;
        }
#pragma unroll
        for (int k = 0; k < 4; k++) {
            int row = ty + 8 * k;
            tile[row][tx] = v[k];
            if (tch[k]) s[(size_t)row * CDIM + tx] = 0.0f;  // restore invariant
        }
        __syncthreads();

        float* dst = dst0 + t * 32;
        float r = crec[buf][tx];
#pragma unroll
        for (int k = 0; k < 4; k++) {
            int ch = ty + 8 * k;
            dst[(size_t)ch * R2 + tx] = __fmul_rn(tile[tx][ch], r);
        }
        __syncthreads();   // tile reuse next iteration
    }
}

// merged transpose: flat grid decodes (scale, tile, b, p)
// scale2 (sparse pipe): 512 tile4 * 24 = 12288
// scale1 (dense):       512 tiles * 24 = 12288
// scale0 (dense):       128 tiles * 24 = 3072
#define TRA 12288
#define TRB (TRA + 12288)
#define TR_TOTAL (TRB + 3072)

__global__ __launch_bounds__(256)
void transpose_all_kernel(float* __restrict__ out) {
    int blk = blockIdx.x;
    if (blk < TRA) {
        int tile = blk & 511, bp = blk >> 9;
        sparse_pipe_body(out + OFF2, OFF2, CNT2, tile, bp & 7, bp >> 3);
    } else if (blk < TRB) {
        int q = blk - TRA;
        int tile = q & 511, bp = q >> 9;
        dense_body<128>(out + OFF1, OFF1, CNT1, tile, bp & 7, bp >> 3);
    } else {
        int q = blk - TRB;
        int tile = q & 127, bp = q >> 7;
        dense_body<64>(out + OFF0, OFF0, CNT0, tile, bp & 7, bp >> 3);
    }
}

// ---------------------------------------------------------------------------

extern "C" void kernel_launch(void* const* d_in, const int* in_sizes, int n_in,
                              void* d_out, int out_size) {
    // Match inputs by element count (all six are distinct).
    const float *f0 = nullptr, *f1 = nullptr, *f2 = nullptr;
    const float *c0 = nullptr, *c1 = nullptr, *c2 = nullptr;
    for (int i = 0; i < n_in; i++) {
        int s = in_sizes[i];
        const float* p = (const float*)d_in[i];
        if (s == 8 * 65536 * 32) f0 = p;
        else if (s == 8 * 32768 * 32) f1 = p;
        else if (s == 8 * 16384 * 32) f2 = p;
        else if (s == 8 * 65536 * 3) c0 = p;
        else if (s == 8 * 32768 * 3) c1 = p;
        else if (s == 8 * 16384 * 3) c2 = p;
    }

    float* out = (float*)d_out;

    // scatter all scales (scratch all-zero on entry by invariant)
    scatter_all_kernel<<<3584, 256>>>(f0, c0, f1, c1, f2, c2);

    // transpose + divide into d_out; restores scratch/count zeros
    transpose_all_kernel<<<TR_TOTAL, dim3(32, 8)>>>(out);
}

// round 10
// speedup vs baseline: 1.2258x; 1.2258x over previous
#include <cuda_runtime.h>
#include <cstdint>

// ---------------------------------------------------------------------------
// Multi-scale triplane encoder: scatter-mean of point features into 3 planes
// per scale. B=8, C=32, scales: (res=64, N=65536), (128, 32768), (256, 16384).
//
// Scatter: red.global.add.v4.f32 into channel-contiguous scratch (p,b,cell,C).
// Transpose: dense smem transpose (+count divide), MLP=4 front loads, one
// barrier (the only structure measured at ~3 TB/s on this problem).
//
// Phase overlap (same stream, 3 launches, no extra sync):
//   K1: scatter scale2                      (~22us)
//   K2: scatter scale0+1  ||  transpose scale2   (independent -> co-resident)
//   K3: transpose scale1+0
//
// Scratch invariant: g_scr/g_cnt ALL-ZERO between kernel_launch calls
// (counts zeroed by their loader thread, touched lines zeroed by predicated
// stores after the barrier). No separate zero pass ever runs.
// ---------------------------------------------------------------------------

#define BATCH 8
#define CDIM 32

#define SCR_TOTAL 66060288          // 264MB scratch (same count as output)
__device__ __align__(16) float g_scr[SCR_TOTAL];
#define CNT_TOTAL 2064384
__device__ __align__(16) float g_cnt[CNT_TOTAL];

// scale bases (floats) — same for scratch and output
#define OFF0 0
#define OFF1 (3 * 8 * 32 * 64 * 64)                 //  3,145,728
#define OFF2 (OFF1 + 3 * 8 * 32 * 128 * 128)        // 15,728,640
#define CNT0 0
#define CNT1 (3 * 8 * 64 * 64)                      //  98,304
#define CNT2 (CNT1 + 3 * 8 * 128 * 128)             // 491,520

// ---------------------------------------------------------------------------
// Index math must match XLA bit-for-bit: x/C -> x*(1/C) (f32 folded), no FMA.
// ---------------------------------------------------------------------------

__device__ __forceinline__ int grid_idx(float v, float res) {
    const float R = (float)(1.0 / (double)1.10001f);
    float u = __fadd_rn(__fmul_rn(v, R), 0.5f);       // no fma contraction
    u = fminf(fmaxf(u, 0.0f), 0.99999f);
    return (int)(__fmul_rn(u, res));
}

__device__ __forceinline__ void red_v4(float* p, float a, float b, float c, float d) {
    asm volatile("red.global.add.v4.f32 [%0], {%1, %2, %3, %4};"
                 :: "l"(p), "f"(a), "f"(b), "f"(c), "f"(d)
                 : "memory");
}

template <int RES, int LOGN>
__device__ __forceinline__ void scatter_body(const float* __restrict__ f,
                                             const float* __restrict__ cd,
                                             int scr_off, int cnt_off, int gid) {
    const int R2 = RES * RES;
    int b = gid >> LOGN;

    float4 feat[CDIM / 4];
    const float4* fv = reinterpret_cast<const float4*>(f + (size_t)gid * CDIM);
#pragma unroll
    for (int i = 0; i < CDIM / 4; i++) feat[i] = fv[i];
    float x = cd[gid * 3 + 0];
    float y = cd[gid * 3 + 1];
    float z = cd[gid * 3 + 2];

    int gx = grid_idx(x, (float)RES);
    int gy = grid_idx(y, (float)RES);
    int gz = grid_idx(z, (float)RES);

    int idx[3];
    idx[0] = gx + RES * gz;   // xz
    idx[1] = gx + RES * gy;   // xy
    idx[2] = gy + RES * gz;   // yz

#pragma unroll
    for (int p = 0; p < 3; p++) {
        atomicAdd(&g_cnt[cnt_off + ((size_t)p * BATCH + b) * R2 + idx[p]], 1.0f);
        float* o = g_scr + scr_off +
                   (((size_t)p * BATCH + b) * R2 + idx[p]) * CDIM;  // 128B line
#pragma unroll
        for (int i = 0; i < CDIM / 4; i++) {
            red_v4(o + 4 * i, feat[i].x, feat[i].y, feat[i].z, feat[i].w);
        }
    }
}

// ---------------------------------------------------------------------------
// Dense transpose body: MLP=4 front loads, one barrier. Caller provides smem.
// ---------------------------------------------------------------------------

struct TBuf {
    float tile[32][33];
    float scnt[32];
    float crec[32];
};

template <int RES>
__device__ __forceinline__ void dense_body(float* __restrict__ out,
                                           int scr_off, int cnt_off,
                                           int tile_idx, int b, int p,
                                           int tx, int ty, TBuf* sb) {
    const int R2 = RES * RES;
    int cell0 = tile_idx * 32;

    size_t base = ((size_t)p * BATCH + b) * R2;
    float* cnt = g_cnt + cnt_off + base + cell0;
    float* src = g_scr + scr_off + (base + cell0) * CDIM;

    float v[4];
#pragma unroll
    for (int k = 0; k < 4; k++) v[k] = src[(size_t)(ty + 8 * k) * CDIM + tx];

    if (ty == 0) {
        float c = cnt[tx];
        cnt[tx] = 0.0f;                       // restore count invariant
        sb->scnt[tx] = c;
        sb->crec[tx] = __frcp_rn(fmaxf(c, 1.0f));
    }

#pragma unroll
    for (int k = 0; k < 4; k++) sb->tile[ty + 8 * k][tx] = v[k];
    __syncthreads();

#pragma unroll
    for (int k = 0; k < 4; k++) {
        int row = ty + 8 * k;
        if (sb->scnt[row] != 0.0f) src[(size_t)row * CDIM + tx] = 0.0f;
    }

    float* dst = out + base * CDIM + cell0;
    float r = sb->crec[tx];
#pragma unroll
    for (int k = 0; k < 4; k++) {
        int ch = ty + 8 * k;
        dst[(size_t)ch * R2 + tx] = __fmul_rn(sb->tile[tx][ch], r);
    }
}

// ---------------------------------------------------------------------------
// K1: scatter scale2 (512 blocks)
// ---------------------------------------------------------------------------
__global__ __launch_bounds__(256)
void k1_scatter2(const float* __restrict__ f2, const float* __restrict__ c2) {
    scatter_body<256, 14>(f2, c2, OFF2, CNT2, blockIdx.x * 256 + threadIdx.x);
}

// ---------------------------------------------------------------------------
// K2: scatter scale0 [0,2048) + scale1 [2048,3072)  ||  transpose scale2
//     [3072, 3072+49152). Scatter blocks first so they start in wave 1.
// ---------------------------------------------------------------------------
#define K2_TOTAL (3072 + 49152)

__global__ __launch_bounds__(256)
void k2_mixed(const float* __restrict__ f0, const float* __restrict__ c0,
              const float* __restrict__ f1, const float* __restrict__ c1,
              float* __restrict__ out) {
    __shared__ TBuf sb;
    int blk = blockIdx.x;
    int t = threadIdx.x;
    if (blk < 2048) {
        scatter_body<64, 16>(f0, c0, OFF0, CNT0, blk * 256 + t);
    } else if (blk < 3072) {
        scatter_body<128, 15>(f1, c1, OFF1, CNT1, (blk - 2048) * 256 + t);
    } else {
        int q = blk - 3072;
        int tile = q & 2047, bp = q >> 11;      // 2048 tiles, 24 (b,p)
        dense_body<256>(out + OFF2, OFF2, CNT2, tile, bp & 7, bp >> 3,
                        t & 31, t >> 5, &sb);
    }
}

// ---------------------------------------------------------------------------
// K3: transpose scale1 [0,12288) + scale0 [12288,15360)
// ---------------------------------------------------------------------------
#define K3_TOTAL (12288 + 3072)

__global__ __launch_bounds__(256)
void k3_transpose01(float* __restrict__ out) {
    __shared__ TBuf sb;
    int blk = blockIdx.x;
    int t = threadIdx.x;
    if (blk < 12288) {
        int tile = blk & 511, bp = blk >> 9;
        dense_body<128>(out + OFF1, OFF1, CNT1, tile, bp & 7, bp >> 3,
                        t & 31, t >> 5, &sb);
    } else {
        int q = blk - 12288;
        int tile = q & 127, bp = q >> 7;
        dense_body<64>(out + OFF0, OFF0, CNT0, tile, bp & 7, bp >> 3,
                       t & 31, t >> 5, &sb);
    }
}

// ---------------------------------------------------------------------------

extern "C" void kernel_launch(void* const* d_in, const int* in_sizes, int n_in,
                              void* d_out, int out_size) {
    // Match inputs by element count (all six are distinct).
    const float *f0 = nullptr, *f1 = nullptr, *f2 = nullptr;
    const float *c0 = nullptr, *c1 = nullptr, *c2 = nullptr;
    for (int i = 0; i < n_in; i++) {
        int s = in_sizes[i];
        const float* p = (const float*)d_in[i];
        if (s == 8 * 65536 * 32) f0 = p;
        else if (s == 8 * 32768 * 32) f1 = p;
        else if (s == 8 * 16384 * 32) f2 = p;
        else if (s == 8 * 65536 * 3) c0 = p;
        else if (s == 8 * 32768 * 3) c1 = p;
        else if (s == 8 * 16384 * 3) c2 = p;
    }

    float* out = (float*)d_out;

    k1_scatter2<<<512, 256>>>(f2, c2);                         // scatter s2
    k2_mixed<<<K2_TOTAL, 256>>>(f0, c0, f1, c1, out);          // s0+s1 || t2
    k3_transpose01<<<K3_TOTAL, 256>>>(out);                    // t1+t0
}

// round 11
// speedup vs baseline: 1.2551x; 1.0239x over previous
#include <cuda_runtime.h>
#include <cstdint>

// ---------------------------------------------------------------------------
// Multi-scale triplane encoder: scatter-mean of point features into 3 planes
// per scale. B=8, C=32, scales: (res=64, N=65536), (128, 32768), (256, 16384).
//
// Scatter: red.global.add.v4.f32 into channel-contiguous scratch (p,b,cell,C).
// Transpose: dense smem transpose (+count divide), MLP=4 front loads, one
// barrier (the only structure measured at ~3 TB/s on this problem).
//
// Phase overlap (same stream, 3 launches, no extra sync):
//   K1: scatter scale2                      (~22us)
//   K2: scatter scale0+1  ||  transpose scale2   (independent -> co-resident)
//   K3: transpose scale1+0
//
// Scratch invariant: g_scr/g_cnt ALL-ZERO between kernel_launch calls
// (counts zeroed by their loader thread, touched lines zeroed by predicated
// stores after the barrier). No separate zero pass ever runs.
// ---------------------------------------------------------------------------

#define BATCH 8
#define CDIM 32

#define SCR_TOTAL 66060288          // 264MB scratch (same count as output)
__device__ __align__(16) float g_scr[SCR_TOTAL];
#define CNT_TOTAL 2064384
__device__ __align__(16) float g_cnt[CNT_TOTAL];

// scale bases (floats) — same for scratch and output
#define OFF0 0
#define OFF1 (3 * 8 * 32 * 64 * 64)                 //  3,145,728
#define OFF2 (OFF1 + 3 * 8 * 32 * 128 * 128)        // 15,728,640
#define CNT0 0
#define CNT1 (3 * 8 * 64 * 64)                      //  98,304
#define CNT2 (CNT1 + 3 * 8 * 128 * 128)             // 491,520

// ---------------------------------------------------------------------------
// Index math must match XLA bit-for-bit: x/C -> x*(1/C) (f32 folded), no FMA.
// ---------------------------------------------------------------------------

__device__ __forceinline__ int grid_idx(float v, float res) {
    const float R = (float)(1.0 / (double)1.10001f);
    float u = __fadd_rn(__fmul_rn(v, R), 0.5f);       // no fma contraction
    u = fminf(fmaxf(u, 0.0f), 0.99999f);
    return (int)(__fmul_rn(u, res));
}

__device__ __forceinline__ void red_v4(float* p, float a, float b, float c, float d) {
    asm volatile("red.global.add.v4.f32 [%0], {%1, %2, %3, %4};"
                 :: "l"(p), "f"(a), "f"(b), "f"(c), "f"(d)
                 : "memory");
}

template <int RES, int LOGN>
__device__ __forceinline__ void scatter_body(const float* __restrict__ f,
                                             const float* __restrict__ cd,
                                             int scr_off, int cnt_off, int gid) {
    const int R2 = RES * RES;
    int b = gid >> LOGN;

    float4 feat[CDIM / 4];
    const float4* fv = reinterpret_cast<const float4*>(f + (size_t)gid * CDIM);
#pragma unroll
    for (int i = 0; i < CDIM / 4; i++) feat[i] = fv[i];
    float x = cd[gid * 3 + 0];
    float y = cd[gid * 3 + 1];
    float z = cd[gid * 3 + 2];

    int gx = grid_idx(x, (float)RES);
    int gy = grid_idx(y, (float)RES);
    int gz = grid_idx(z, (float)RES);

    int idx[3];
    idx[0] = gx + RES * gz;   // xz
    idx[1] = gx + RES * gy;   // xy
    idx[2] = gy + RES * gz;   // yz

#pragma unroll
    for (int p = 0; p < 3; p++) {
        atomicAdd(&g_cnt[cnt_off + ((size_t)p * BATCH + b) * R2 + idx[p]], 1.0f);
        float* o = g_scr + scr_off +
                   (((size_t)p * BATCH + b) * R2 + idx[p]) * CDIM;  // 128B line
#pragma unroll
        for (int i = 0; i < CDIM / 4; i++) {
            red_v4(o + 4 * i, feat[i].x, feat[i].y, feat[i].z, feat[i].w);
        }
    }
}

// ---------------------------------------------------------------------------
// Dense transpose body: MLP=4 front loads, one barrier. Caller provides smem.
// ---------------------------------------------------------------------------

struct TBuf {
    float tile[32][33];
    float scnt[32];
    float crec[32];
};

template <int RES>
__device__ __forceinline__ void dense_body(float* __restrict__ out,
                                           int scr_off, int cnt_off,
                                           int tile_idx, int b, int p,
                                           int tx, int ty, TBuf* sb) {
    const int R2 = RES * RES;
    int cell0 = tile_idx * 32;

    size_t base = ((size_t)p * BATCH + b) * R2;
    float* cnt = g_cnt + cnt_off + base + cell0;
    float* src = g_scr + scr_off + (base + cell0) * CDIM;

    float v[4];
#pragma unroll
    for (int k = 0; k < 4; k++) v[k] = src[(size_t)(ty + 8 * k) * CDIM + tx];

    if (ty == 0) {
        float c = cnt[tx];
        cnt[tx] = 0.0f;                       // restore count invariant
        sb->scnt[tx] = c;
        sb->crec[tx] = __frcp_rn(fmaxf(c, 1.0f));
    }

#pragma unroll
    for (int k = 0; k < 4; k++) sb->tile[ty + 8 * k][tx] = v[k];
    __syncthreads();

#pragma unroll
    for (int k = 0; k < 4; k++) {
        int row = ty + 8 * k;
        if (sb->scnt[row] != 0.0f) src[(size_t)row * CDIM + tx] = 0.0f;
    }

    float* dst = out + base * CDIM + cell0;
    float r = sb->crec[tx];
#pragma unroll
    for (int k = 0; k < 4; k++) {
        int ch = ty + 8 * k;
        dst[(size_t)ch * R2 + tx] = __fmul_rn(sb->tile[tx][ch], r);
    }
}

// ---------------------------------------------------------------------------
// K1: scatter scale2 (512 blocks)
// ---------------------------------------------------------------------------
__global__ __launch_bounds__(256)
void k1_scatter2(const float* __restrict__ f2, const float* __restrict__ c2) {
    scatter_body<256, 14>(f2, c2, OFF2, CNT2, blockIdx.x * 256 + threadIdx.x);
}

// ---------------------------------------------------------------------------
// K2: scatter scale0 [0,2048) + scale1 [2048,3072)  ||  transpose scale2
//     [3072, 3072+49152). Scatter blocks first so they start in wave 1.
// ---------------------------------------------------------------------------
#define K2_TOTAL (3072 + 49152)

__global__ __launch_bounds__(256)
void k2_mixed(const float* __restrict__ f0, const float* __restrict__ c0,
              const float* __restrict__ f1, const float* __restrict__ c1,
              float* __restrict__ out) {
    __shared__ TBuf sb;
    int blk = blockIdx.x;
    int t = threadIdx.x;
    if (blk < 2048) {
        scatter_body<64, 16>(f0, c0, OFF0, CNT0, blk * 256 + t);
    } else if (blk < 3072) {
        scatter_body<128, 15>(f1, c1, OFF1, CNT1, (blk - 2048) * 256 + t);
    } else {
        int q = blk - 3072;
        int tile = q & 2047, bp = q >> 11;      // 2048 tiles, 24 (b,p)
        dense_body<256>(out + OFF2, OFF2, CNT2, tile, bp & 7, bp >> 3,
                        t & 31, t >> 5, &sb);
    }
}

// ---------------------------------------------------------------------------
// K3: transpose scale1 [0,12288) + scale0 [12288,15360)
// ---------------------------------------------------------------------------
#define K3_TOTAL (12288 + 3072)

__global__ __launch_bounds__(256)
void k3_transpose01(float* __restrict__ out) {
    __shared__ TBuf sb;
    int blk = blockIdx.x;
    int t = threadIdx.x;
    if (blk < 12288) {
        int tile = blk & 511, bp = blk >> 9;
        dense_body<128>(out + OFF1, OFF1, CNT1, tile, bp & 7, bp >> 3,
                        t & 31, t >> 5, &sb);
    } else {
        int q = blk - 12288;
        int tile = q & 127, bp = q >> 7;
        dense_body<64>(out + OFF0, OFF0, CNT0, tile, bp & 7, bp >> 3,
                       t & 31, t >> 5, &sb);
    }
}

// ---------------------------------------------------------------------------

extern "C" void kernel_launch(void* const* d_in, const int* in_sizes, int n_in,
                              void* d_out, int out_size) {
    // Match inputs by element count (all six are distinct).
    const float *f0 = nullptr, *f1 = nullptr, *f2 = nullptr;
    const float *c0 = nullptr, *c1 = nullptr, *c2 = nullptr;
    for (int i = 0; i < n_in; i++) {
        int s = in_sizes[i];
        const float* p = (const float*)d_in[i];
        if (s == 8 * 65536 * 32) f0 = p;
        else if (s == 8 * 32768 * 32) f1 = p;
        else if (s == 8 * 16384 * 32) f2 = p;
        else if (s == 8 * 65536 * 3) c0 = p;
        else if (s == 8 * 32768 * 3) c1 = p;
        else if (s == 8 * 16384 * 3) c2 = p;
    }

    float* out = (float*)d_out;

    k1_scatter2<<<512, 256>>>(f2, c2);                         // scatter s2
    k2_mixed<<<K2_TOTAL, 256>>>(f0, c0, f1, c1, out);          // s0+s1 || t2
    k3_transpose01<<<K3_TOTAL, 256>>>(out);                    // t1+t0
}